// round 10
// baseline (speedup 1.0000x reference)
#include <cuda_runtime.h>

#define Bz 4
#define C_IN 32
#define NPIX 4096                        // 64*64 pooled pixels
#define NODES_PER_B (NPIX * C_IN)        // 131072
#define NODES_TOTAL (Bz * NODES_PER_B)   // 524288
#define ADJ_PER_B   ((long)NPIX * NPIX)  // 16777216 floats
#define EPSV 1e-6f

// patch certainty for pooled pixel p of batch b (x_var is 1MB, L2-resident)
__device__ __forceinline__ float certainty(const float4* __restrict__ xv4, int b, int p)
{
    int R = p >> 6, C = p & 63;
    float s = 0.f;
    #pragma unroll
    for (int i = 0; i < 4; ++i) {
        float4 v = __ldg(&xv4[((b * 256 + (R * 4 + i)) << 6) + C]);
        s += v.x + v.y + v.z + v.w;
    }
    return 1.f - s * (1.f / 16.f);
}

// Pool x_feat (channel-summed 4x4) and write tiled nodes. Independent of memset.
// 256 blocks x 256 threads; block owns 1 pooled row.
__global__ __launch_bounds__(256) void pool_nodes(
    const float* __restrict__ x_feat,
    float* __restrict__ out)
{
    __shared__ float red[4][64];         // [quad][Cc] partial sums
    __shared__ float sums[64];

    int blk = blockIdx.x;                // 0..255
    int b   = blk >> 6;                  // batch
    int R   = blk & 63;                  // pooled row

    int tid  = threadIdx.x;              // 0..255
    int quad = tid >> 6;                 // image row within 4x4 patch
    int Cc   = tid & 63;                 // pooled column

    const float4* xf4 = (const float4*)x_feat;
    float acc = 0.f;
    #pragma unroll
    for (int c = 0; c < C_IN; ++c) {
        // 64 lanes read 64 consecutive float4 -> fully coalesced; 32 indep loads
        float4 v = __ldg(&xf4[((((b * C_IN + c) << 8) + (R * 4 + quad)) << 6) + Cc]);
        acc += v.x + v.y + v.z + v.w;
    }
    red[quad][Cc] = acc;
    __syncthreads();

    if (tid < 64)
        sums[tid] = (red[0][tid] + red[1][tid] + red[2][tid] + red[3][tid]) * (1.f / 16.f);
    __syncthreads();

    // nodes: 64 pix x 32 copies = 2048 stores, 8 per thread, coalesced
    float* nodesb = out + (long)b * NODES_PER_B;
    #pragma unroll
    for (int k = 0; k < 8; ++k) {
        int sidx = tid + (k << 8);       // 0..2047
        int j    = sidx >> 6;            // copy 0..31
        int C    = sidx & 63;
        nodesb[j * NPIX + R * 64 + C] = sums[C];
    }
}

// Sparse edge patches; must run after the memset. 64 blocks x 256 threads.
__global__ __launch_bounds__(256) void edge_patch(
    const float* __restrict__ x_var,
    float* __restrict__ out)
{
    int g  = blockIdx.x * 256 + threadIdx.x;   // 0..16383 -> (b, t)
    int b  = g >> 12;
    int t  = g & 4095;
    int R  = t >> 6;
    int Cc = t & 63;

    const float4* xv4 = (const float4*)x_var;
    float xvt = certainty(xv4, b, t);
    float* adjb = out + NODES_TOTAL + (long)b * ADJ_PER_B;

    if (R < 63) {
        float w = certainty(xv4, b, t + 64) - xvt;
        if (w > EPSV) adjb[(long)(t + 64) * NPIX + t] = w;
    }
    if (R > 0) {
        float w = certainty(xv4, b, t - 64) - xvt;
        if (w > EPSV) adjb[(long)(t - 64) * NPIX + t] = w;
    }
    if (Cc < 63) {
        float w = certainty(xv4, b, t + 1) - xvt;
        if (w > EPSV) adjb[(long)(t + 1) * NPIX + t] = w;
    }
    if (Cc > 0) {
        float w = certainty(xv4, b, t - 1) - xvt;
        if (w > EPSV) adjb[(long)(t - 1) * NPIX + t] = w;
    }
}

extern "C" void kernel_launch(void* const* d_in, const int* in_sizes, int n_in,
                              void* d_out, int out_size)
{
    const float* x_feat = (const float*)d_in[0];
    const float* x_var  = (const float*)d_in[1];
    float* out = (float*)d_out;

    // Fork a side stream so the 256MB memset overlaps the pooling kernel.
    // Host-side objects only (no device alloc); not destroyed mid-capture —
    // kernel_launch runs only for correctness + the single capture call.
    cudaStream_t s2;
    cudaStreamCreateWithFlags(&s2, cudaStreamNonBlocking);
    cudaEvent_t eFork, eJoin;
    cudaEventCreateWithFlags(&eFork, cudaEventDisableTiming);
    cudaEventCreateWithFlags(&eJoin, cudaEventDisableTiming);

    cudaEventRecord(eFork, 0);
    cudaStreamWaitEvent(s2, eFork, 0);

    // Branch A (side stream): driver fill of adj (~6.4 TB/s).
    cudaMemsetAsync(out + NODES_TOTAL, 0, (long)Bz * ADJ_PER_B * sizeof(float), s2);

    // Branch B (main stream), concurrent: pooling + nodes.
    pool_nodes<<<256, 256>>>(x_feat, out);

    // Join, then patch sparse edges into the zeroed adj.
    cudaEventRecord(eJoin, s2);
    cudaStreamWaitEvent(0, eJoin, 0);
    edge_patch<<<64, 256>>>(x_var, out);
}